// round 5
// baseline (speedup 1.0000x reference)
#include <cuda_runtime.h>

// Complex-valued attention, B=4 H=8 S=2048 D=64.
// out[2,B,H,S,D] = cv_softmax((Q/8) K^T) @ V  (softmax on |z|, phase kept)
//
// Flash-style, 1 CTA = (head, 64-query tile), 256 threads (16x16), 4x4
// micro-tiles, fp32 via sm_103a fma.rn.f32x2. Round 2: cp.async
// double-buffered K/V, 2 barriers/tile, row-packed PV (P staged transposed,
// V natural layout), rsqrt-fused softmax.

#define SLEN 2048
#define DH   64
#define NTILE 32
#define PLANE (4 * 8 * 2048 * 64)
#define TEMP_INV 0.125f
#define SGN2 0x8000000080000000ULL

static __device__ __forceinline__ unsigned long long ffma2(unsigned long long a,
                                                           unsigned long long b,
                                                           unsigned long long c) {
    unsigned long long d;
    asm("fma.rn.f32x2 %0, %1, %2, %3;" : "=l"(d) : "l"(a), "l"(b), "l"(c));
    return d;
}
static __device__ __forceinline__ unsigned long long fmul2(unsigned long long a,
                                                           unsigned long long b) {
    unsigned long long d;
    asm("mul.rn.f32x2 %0, %1, %2;" : "=l"(d) : "l"(a), "l"(b));
    return d;
}
static __device__ __forceinline__ float2 up2(unsigned long long v) {
    float2 f;
    asm("mov.b64 {%0, %1}, %2;" : "=f"(f.x), "=f"(f.y) : "l"(v));
    return f;
}
static __device__ __forceinline__ unsigned long long pk2(float a, float b) {
    unsigned long long v;
    asm("mov.b64 %0, {%1, %2};" : "=l"(v) : "f"(a), "f"(b));
    return v;
}
static __device__ __forceinline__ void cp16(float* dst, const float4* src) {
    unsigned a = (unsigned)__cvta_generic_to_shared(dst);
    asm volatile("cp.async.cg.shared.global [%0], [%1], 16;" :: "r"(a), "l"(src));
}

__global__ __launch_bounds__(256, 1)
void cvattn_kernel(const float* __restrict__ qr, const float* __restrict__ qi,
                   const float* __restrict__ kr, const float* __restrict__ ki,
                   const float* __restrict__ vr, const float* __restrict__ vi,
                   float* __restrict__ out)
{
    extern __shared__ float sm[];
    float* sQr   = sm;                 // [m][d] swizzled, 4096
    float* sQi   = sm + 4096;
    float* sKb   = sm + 8192;          // [buf][re/im][64x64], 2x8192
    float* sVb   = sm + 24576;         // [buf][re/im][64x64], 2x8192
    float* sPtr_ = sm + 40960;         // P^T [n][m], 4096
    float* sPti_ = sm + 45056;

    const int tid = threadIdx.x;
    const int tx  = tid & 15;
    const int ty  = tid >> 4;
    const int bh  = blockIdx.y;
    const int m0  = blockIdx.x << 6;

    const size_t hoff = (size_t)bh * (SLEN * DH);
    const float4* K4r = (const float4*)(kr + hoff);
    const float4* K4i = (const float4*)(ki + hoff);
    const float4* V4r = (const float4*)(vr + hoff);
    const float4* V4i = (const float4*)(vi + hoff);

    // ---- Q tile once (scaled), swizzled [m][d] ----
    {
        const float4* Q4r = (const float4*)(qr + hoff);
        const float4* Q4i = (const float4*)(qi + hoff);
#pragma unroll
        for (int i = 0; i < 4; ++i) {
            int f4 = tid + (i << 8);
            int m = f4 >> 4, dc = f4 & 15;
            int gi = ((m0 + m) << 4) + dc;
            float4 a = Q4r[gi];
            float4 b = Q4i[gi];
            a.x *= TEMP_INV; a.y *= TEMP_INV; a.z *= TEMP_INV; a.w *= TEMP_INV;
            b.x *= TEMP_INV; b.y *= TEMP_INV; b.z *= TEMP_INV; b.w *= TEMP_INV;
            int sa = (m << 6) + (((dc ^ (m >> 2)) & 15) << 2);
            *(float4*)(sQr + sa) = a;
            *(float4*)(sQi + sa) = b;
        }
    }

    // ---- prefetch K/V tile 0 into buffer 0 ----
#pragma unroll
    for (int i = 0; i < 4; ++i) {
        int f4 = tid + (i << 8);
        int n = f4 >> 4, dc = f4 & 15;
        int gi = (n << 4) + dc;
        int sa = (n << 6) + (((dc ^ (n >> 2)) & 15) << 2);
        cp16(sKb + sa,        K4r + gi);
        cp16(sKb + 4096 + sa, K4i + gi);
        cp16(sVb + sa,        V4r + gi);
        cp16(sVb + 4096 + sa, V4i + gi);
    }
    asm volatile("cp.async.commit_group;" ::: "memory");

    // O accumulators: row-pair packed (rows ty*4+{0,1} | {2,3}), 3 sets
    unsigned long long oA[2][4], oB[2][4], oI[2][4];
#pragma unroll
    for (int p = 0; p < 2; ++p)
#pragma unroll
        for (int c = 0; c < 4; ++c) { oA[p][c] = 0ull; oB[p][c] = 0ull; oI[p][c] = 0ull; }

    float mrun[4] = {-INFINITY, -INFINITY, -INFINITY, -INFINITY};
    float lrun[4] = {0.f, 0.f, 0.f, 0.f};

    asm volatile("cp.async.wait_group 0;" ::: "memory");
    __syncthreads();

    for (int t = 0; t < NTILE; ++t) {
        const int cur = t & 1;
        float* kb = sKb + (cur << 13);
        float* vb = sVb + (cur << 13);

        // ---- prefetch next tile into the other buffer ----
        if (t + 1 < NTILE) {
            float* kn = sKb + ((cur ^ 1) << 13);
            float* vn = sVb + ((cur ^ 1) << 13);
#pragma unroll
            for (int i = 0; i < 4; ++i) {
                int f4 = tid + (i << 8);
                int n = f4 >> 4, dc = f4 & 15;
                int gi = ((((t + 1) << 6) + n) << 4) + dc;
                int sa = (n << 6) + (((dc ^ (n >> 2)) & 15) << 2);
                cp16(kn + sa,        K4r + gi);
                cp16(kn + 4096 + sa, K4i + gi);
                cp16(vn + sa,        V4r + gi);
                cp16(vn + 4096 + sa, V4i + gi);
            }
        }
        asm volatile("cp.async.commit_group;" ::: "memory");

        // ---- S = (Q/T) K^T  (complex), reduction-packed over d ----
        unsigned long long sre[4][4], sim[4][4];
#pragma unroll
        for (int r = 0; r < 4; ++r)
#pragma unroll
            for (int c = 0; c < 4; ++c) { sre[r][c] = 0ull; sim[r][c] = 0ull; }

#pragma unroll 4
        for (int kc = 0; kc < 16; ++kc) {
            ulonglong2 aR[4], aI[4];
            int qoff = ((kc ^ ty) & 15) << 2;
#pragma unroll
            for (int r = 0; r < 4; ++r) {
                int row = (ty << 2) + r;
                aR[r] = *(const ulonglong2*)(sQr + (row << 6) + qoff);
                aI[r] = *(const ulonglong2*)(sQi + (row << 6) + qoff);
            }
            int koff = ((kc ^ tx) & 15) << 2;
#pragma unroll
            for (int c = 0; c < 4; ++c) {
                int col = (tx << 2) + c;
                const float* kp = kb + (col << 6) + koff;
                ulonglong2 bR = *(const ulonglong2*)kp;
                ulonglong2 bI = *(const ulonglong2*)(kp + 4096);
                unsigned long long nbx = bI.x ^ SGN2;
                unsigned long long nby = bI.y ^ SGN2;
#pragma unroll
                for (int r = 0; r < 4; ++r) {
                    sre[r][c] = ffma2(aR[r].x, bR.x, sre[r][c]);
                    sre[r][c] = ffma2(aR[r].y, bR.y, sre[r][c]);
                    sre[r][c] = ffma2(aI[r].x, nbx, sre[r][c]);
                    sre[r][c] = ffma2(aI[r].y, nby, sre[r][c]);
                    sim[r][c] = ffma2(aR[r].x, bI.x, sim[r][c]);
                    sim[r][c] = ffma2(aR[r].y, bI.y, sim[r][c]);
                    sim[r][c] = ffma2(aI[r].x, bR.x, sim[r][c]);
                    sim[r][c] = ffma2(aI[r].y, bR.y, sim[r][c]);
                }
            }
        }

        // ---- online magnitude-softmax ----
        float prv[4][4], piv[4][4], sc[4];
#pragma unroll
        for (int r = 0; r < 4; ++r) {
            float re[4], im[4], mg[4], ri[4];
            float rowmax = -INFINITY;
#pragma unroll
            for (int c = 0; c < 4; ++c) {
                float2 e = up2(sre[r][c]);
                float2 f = up2(sim[r][c]);
                re[c] = e.x + e.y;
                im[c] = f.x + f.y;
                float r2 = re[c] * re[c] + im[c] * im[c];
                ri[c] = rsqrtf(fmaxf(r2, 1e-24f));   // = 1/max(|z|,1e-12)
                mg[c] = r2 * ri[c];                  // = |z| (0 at z=0)
                rowmax = fmaxf(rowmax, mg[c]);
            }
#pragma unroll
            for (int o = 8; o >= 1; o >>= 1)
                rowmax = fmaxf(rowmax, __shfl_xor_sync(0xffffffffu, rowmax, o, 16));
            float mn = fmaxf(mrun[r], rowmax);
            sc[r] = __expf(mrun[r] - mn);
            float ps = 0.f;
#pragma unroll
            for (int c = 0; c < 4; ++c) {
                float p = __expf(mg[c] - mn);
                ps += p;
                float w = p * ri[c];
                prv[r][c] = re[c] * w;
                piv[r][c] = im[c] * w;
            }
#pragma unroll
            for (int o = 8; o >= 1; o >>= 1)
                ps += __shfl_xor_sync(0xffffffffu, ps, o, 16);
            lrun[r] = lrun[r] * sc[r] + ps;
            mrun[r] = mn;
        }
        // rescale O (row-pair packed)
        {
            unsigned long long s01 = pk2(sc[0], sc[1]);
            unsigned long long s23 = pk2(sc[2], sc[3]);
#pragma unroll
            for (int c = 0; c < 4; ++c) {
                oA[0][c] = fmul2(oA[0][c], s01); oA[1][c] = fmul2(oA[1][c], s23);
                oB[0][c] = fmul2(oB[0][c], s01); oB[1][c] = fmul2(oB[1][c], s23);
                oI[0][c] = fmul2(oI[0][c], s01); oI[1][c] = fmul2(oI[1][c], s23);
            }
        }
        // store P^T [n][m] (vectorized over the thread's 4 rows)
#pragma unroll
        for (int c = 0; c < 4; ++c) {
            int n = (tx << 2) + c;
            int sa = (n << 6) + (((ty ^ tx) & 15) << 2);
            *(float4*)(sPtr_ + sa) = make_float4(prv[0][c], prv[1][c], prv[2][c], prv[3][c]);
            *(float4*)(sPti_ + sa) = make_float4(piv[0][c], piv[1][c], piv[2][c], piv[3][c]);
        }
        __syncthreads();   // P^T visible to all

        // ---- O += P V  (row-pair packed; V natural [n][d]) ----
        //  oA += pr*vr ; oB += pi*vi ; oI += pr*vi + pi*vr ;  O_re = oA - oB
#pragma unroll 2
        for (int nc = 0; nc < 16; ++nc) {
            int poff = ((ty ^ nc) & 15) << 2;
            int voff = ((tx ^ nc) & 15) << 2;
#pragma unroll
            for (int j = 0; j < 4; ++j) {
                int n = (nc << 2) + j;
                const float* pp = sPtr_ + (n << 6) + poff;
                ulonglong2 pR = *(const ulonglong2*)pp;
                ulonglong2 pI = *(const ulonglong2*)(pp + 4096);
                const float* vp = vb + (n << 6) + voff;
                float4 v_r = *(const float4*)vp;
                float4 v_i = *(const float4*)(vp + 4096);
#pragma unroll
                for (int c = 0; c < 4; ++c) {
                    unsigned long long vrb = pk2((&v_r.x)[c], (&v_r.x)[c]);
                    unsigned long long vib = pk2((&v_i.x)[c], (&v_i.x)[c]);
                    oA[0][c] = ffma2(pR.x, vrb, oA[0][c]);
                    oA[1][c] = ffma2(pR.y, vrb, oA[1][c]);
                    oB[0][c] = ffma2(pI.x, vib, oB[0][c]);
                    oB[1][c] = ffma2(pI.y, vib, oB[1][c]);
                    oI[0][c] = ffma2(pR.x, vib, oI[0][c]);
                    oI[1][c] = ffma2(pR.y, vib, oI[1][c]);
                    oI[0][c] = ffma2(pI.x, vrb, oI[0][c]);
                    oI[1][c] = ffma2(pI.y, vrb, oI[1][c]);
                }
            }
        }

        asm volatile("cp.async.wait_group 0;" ::: "memory");
        __syncthreads();   // next K/V ready; P^T consumed
    }

    // ---- epilogue ----
    float4* OutR = (float4*)(out + hoff);
    float4* OutI = (float4*)(out + (size_t)PLANE + hoff);
    float invl[4];
#pragma unroll
    for (int r = 0; r < 4; ++r) invl[r] = 1.0f / lrun[r];
#pragma unroll
    for (int p = 0; p < 2; ++p) {
        float4 oR0, oI0, oR1, oI1;
        float i0 = invl[p * 2], i1 = invl[p * 2 + 1];
#pragma unroll
        for (int c = 0; c < 4; ++c) {
            float2 ea = up2(oA[p][c]);
            float2 eb = up2(oB[p][c]);
            float2 fi = up2(oI[p][c]);
            (&oR0.x)[c] = (ea.x - eb.x) * i0;
            (&oI0.x)[c] = fi.x * i0;
            (&oR1.x)[c] = (ea.y - eb.y) * i1;
            (&oI1.x)[c] = fi.y * i1;
        }
        int row0 = m0 + (ty << 2) + p * 2;
        int gi0 = (row0 << 4) + tx;
        int gi1 = ((row0 + 1) << 4) + tx;
        OutR[gi0] = oR0; OutI[gi0] = oI0;
        OutR[gi1] = oR1; OutI[gi1] = oI1;
    }
}

extern "C" void kernel_launch(void* const* d_in, const int* in_sizes, int n_in,
                              void* d_out, int out_size)
{
    (void)in_sizes; (void)n_in; (void)out_size;
    cudaFuncSetAttribute(cvattn_kernel,
                         cudaFuncAttributeMaxDynamicSharedMemorySize, 196608);
    dim3 grid(SLEN / 64, 32);
    cvattn_kernel<<<grid, 256, 196608>>>(
        (const float*)d_in[0], (const float*)d_in[1],
        (const float*)d_in[2], (const float*)d_in[3],
        (const float*)d_in[4], (const float*)d_in[5],
        (float*)d_out);
}

// round 8
// speedup vs baseline: 3.2702x; 3.2702x over previous
#include <cuda_runtime.h>
#include <cstdint>

// Complex attention via portable mma.sync tf32 (legacy HMMA on sm_103).
// 1 CTA = 128 query rows of one head; 8 warps x 16 rows.
// Round 8: K/V pre-rounded to tf32-RNA in a prepass (kills HW-truncation bias);
// P rounded RNA at smem store. Numerics only; hot loops unchanged from R7.
#define SLEN 2048
#define PLANE (4*8*2048*64)
#define TEMP_INV 0.125f
#define NT 32

// smem float offsets
#define SK 0                  // K: [buf][plane][64][68]
#define K_PL 4352
#define K_BUF 8704
#define SV 17408              // V: [buf][plane][64][72]
#define V_PL 4608
#define V_BUF 9216
#define SP 35840              // P: [warp][plane][16][68]
#define P_PL 1088
#define P_W 2176
#define SMEM_BYTES ((35840 + 8*2176)*4)   // 212992

// tf32-rounded copies of K/V (re,im): 4 x 16MB scratch
__device__ float g_kv[4][PLANE];

static __device__ __forceinline__ void mma8(float* d, const uint32_t* a,
                                            uint32_t b0, uint32_t b1) {
    asm volatile("mma.sync.aligned.m16n8k8.row.col.f32.tf32.tf32.f32 "
                 "{%0,%1,%2,%3},{%4,%5,%6,%7},{%8,%9},{%0,%1,%2,%3};"
                 : "+f"(d[0]), "+f"(d[1]), "+f"(d[2]), "+f"(d[3])
                 : "r"(a[0]), "r"(a[1]), "r"(a[2]), "r"(a[3]), "r"(b0), "r"(b1));
}
static __device__ __forceinline__ uint32_t tf32r(float x) {
    uint32_t u; asm("cvt.rna.tf32.f32 %0, %1;" : "=r"(u) : "f"(x)); return u;
}
static __device__ __forceinline__ void cp16(float* dst, const float4* src) {
    unsigned a = (unsigned)__cvta_generic_to_shared(dst);
    asm volatile("cp.async.cg.shared.global [%0], [%1], 16;" :: "r"(a), "l"(src));
}

// ---- prepass: elementwise tf32-RNA rounding of K/V into scratch ----
__global__ __launch_bounds__(256)
void round_kv(const float4* __restrict__ kr, const float4* __restrict__ ki,
              const float4* __restrict__ vr, const float4* __restrict__ vi)
{
    const int a = blockIdx.y;
    const float4* src = (a == 0) ? kr : (a == 1) ? ki : (a == 2) ? vr : vi;
    float4* dst = (float4*)g_kv[a];
    int i = blockIdx.x * 256 + threadIdx.x;
    float4 v = src[i];
    v.x = __uint_as_float(tf32r(v.x));
    v.y = __uint_as_float(tf32r(v.y));
    v.z = __uint_as_float(tf32r(v.z));
    v.w = __uint_as_float(tf32r(v.w));
    dst[i] = v;
}

static __device__ __forceinline__ void load_tile(float* sm, int tid, int buf, int gb,
    const float4* K4r, const float4* K4i, const float4* V4r, const float4* V4i)
{
    float* kd = sm + SK + buf * K_BUF;
    float* vd = sm + SV + buf * V_BUF;
#pragma unroll
    for (int i = 0; i < 8; ++i) {
        int f = tid + (i << 8);               // 0..2047
        int ch = f & 15, row = (f >> 4) & 63, pl = f >> 10;
        cp16(kd + pl * K_PL + row * 68 + ch * 4, (pl ? K4i : K4r) + ((gb + row) << 4) + ch);
        cp16(vd + pl * V_PL + row * 72 + ch * 4, (pl ? V4i : V4r) + ((gb + row) << 4) + ch);
    }
}

__global__ __launch_bounds__(256, 1)
void cvattn_mma(const float* __restrict__ qr_g, const float* __restrict__ qi_g,
                float* __restrict__ out)
{
    extern __shared__ float sm[];
    const int tid  = threadIdx.x;
    const int w    = tid >> 5;
    const int lane = tid & 31;
    const int g    = lane >> 2;
    const int l    = lane & 3;
    const size_t hoff = (size_t)blockIdx.y * (SLEN * 64);
    const int m0 = blockIdx.x << 7;

    const float4* K4r = (const float4*)(g_kv[0] + hoff);
    const float4* K4i = (const float4*)(g_kv[1] + hoff);
    const float4* V4r = (const float4*)(g_kv[2] + hoff);
    const float4* V4i = (const float4*)(g_kv[3] + hoff);

    // ---- Q fragments (persist in registers, tf32 round-to-nearest) ----
    uint32_t qa[8][4], qb[8][4];
    {
        const float* Qr = qr_g + hoff;
        const float* Qi = qi_g + hoff;
        const int r0 = (m0 + w * 16 + g) * 64;
        const int r1 = r0 + 8 * 64;
#pragma unroll
        for (int kt = 0; kt < 8; ++kt) {
            int c = kt * 8 + l;
            qa[kt][0] = tf32r(Qr[r0 + c] * TEMP_INV);
            qa[kt][1] = tf32r(Qr[r1 + c] * TEMP_INV);
            qa[kt][2] = tf32r(Qr[r0 + c + 4] * TEMP_INV);
            qa[kt][3] = tf32r(Qr[r1 + c + 4] * TEMP_INV);
            qb[kt][0] = tf32r(Qi[r0 + c] * TEMP_INV);
            qb[kt][1] = tf32r(Qi[r1 + c] * TEMP_INV);
            qb[kt][2] = tf32r(Qi[r0 + c + 4] * TEMP_INV);
            qb[kt][3] = tf32r(Qi[r1 + c + 4] * TEMP_INV);
        }
    }

    float ore[8][4], oim[8][4];
#pragma unroll
    for (int nt = 0; nt < 8; ++nt)
#pragma unroll
        for (int j = 0; j < 4; ++j) { ore[nt][j] = 0.f; oim[nt][j] = 0.f; }
    float lsum0 = 0.f, lsum1 = 0.f;

    load_tile(sm, tid, 0, 0, K4r, K4i, V4r, V4i);
    asm volatile("cp.async.commit_group;" ::: "memory");
    asm volatile("cp.async.wait_group 0;" ::: "memory");
    __syncthreads();

    float* pw = sm + SP + w * P_W;   // this warp's P region (re at 0, im at +P_PL)

    for (int t = 0; t < NT; ++t) {
        if (t + 1 < NT)
            load_tile(sm, tid, (t + 1) & 1, (t + 1) << 6, K4r, K4i, V4r, V4i);
        asm volatile("cp.async.commit_group;" ::: "memory");

        const float* ks = sm + SK + (t & 1) * K_BUF;   // Kr
        const float* ki = ks + K_PL;                   // Ki

        // ---- S = (Q/T) K^T : complex, via sign-flip on Ki fragment ----
        float sre[8][4], sim_[8][4];
#pragma unroll
        for (int nt = 0; nt < 8; ++nt)
#pragma unroll
            for (int j = 0; j < 4; ++j) { sre[nt][j] = 0.f; sim_[nt][j] = 0.f; }

#pragma unroll
        for (int kt = 0; kt < 8; ++kt) {
            const int krow = kt * 8 + l;
#pragma unroll
            for (int nt = 0; nt < 8; ++nt) {
                const int ncol = (nt * 8 + g) * 68;
                uint32_t br0 = __float_as_uint(ks[ncol + krow]);
                uint32_t br1 = __float_as_uint(ks[ncol + krow + 4]);
                uint32_t bi0 = __float_as_uint(ki[ncol + krow]);
                uint32_t bi1 = __float_as_uint(ki[ncol + krow + 4]);
                mma8(sre[nt], qa[kt], br0, br1);
                mma8(sre[nt], qb[kt], bi0 ^ 0x80000000u, bi1 ^ 0x80000000u);
                mma8(sim_[nt], qa[kt], bi0, bi1);
                mma8(sim_[nt], qb[kt], br0, br1);
            }
        }

        // ---- softmax on |S| (no max subtraction); P -> warp-private smem ----
#pragma unroll
        for (int nt = 0; nt < 8; ++nt) {
            float pr[4], pi[4];
#pragma unroll
            for (int j = 0; j < 4; ++j) {
                float x = sre[nt][j], y = sim_[nt][j];
                float r2 = fmaf(x, x, y * y);
                float ri = rsqrtf(fmaxf(r2, 1e-24f));
                float e  = __expf(r2 * ri);           // exp(|z|)
                float wt = e * ri;
                pr[j] = __uint_as_float(tf32r(x * wt));
                pi[j] = __uint_as_float(tf32r(y * wt));
                if (j < 2) lsum0 += e; else lsum1 += e;
            }
            int c = nt * 8 + 2 * l;
            *(float2*)(pw + g * 68 + c)        = make_float2(pr[0], pr[1]);
            *(float2*)(pw + (g + 8) * 68 + c)  = make_float2(pr[2], pr[3]);
            *(float2*)(pw + P_PL + g * 68 + c)       = make_float2(pi[0], pi[1]);
            *(float2*)(pw + P_PL + (g + 8) * 68 + c) = make_float2(pi[2], pi[3]);
        }
        __syncwarp();

        // ---- O += P V (complex) ----
        const float* vs = sm + SV + (t & 1) * V_BUF;   // Vr
        const float* vi = vs + V_PL;                   // Vi
#pragma unroll
        for (int kt = 0; kt < 8; ++kt) {
            const int pc = kt * 8 + l;
            uint32_t ap[4], ai[4], ain[4];
            ap[0] = __float_as_uint(pw[g * 68 + pc]);
            ap[1] = __float_as_uint(pw[(g + 8) * 68 + pc]);
            ap[2] = __float_as_uint(pw[g * 68 + pc + 4]);
            ap[3] = __float_as_uint(pw[(g + 8) * 68 + pc + 4]);
            ai[0] = __float_as_uint(pw[P_PL + g * 68 + pc]);
            ai[1] = __float_as_uint(pw[P_PL + (g + 8) * 68 + pc]);
            ai[2] = __float_as_uint(pw[P_PL + g * 68 + pc + 4]);
            ai[3] = __float_as_uint(pw[P_PL + (g + 8) * 68 + pc + 4]);
#pragma unroll
            for (int j = 0; j < 4; ++j) ain[j] = ai[j] ^ 0x80000000u;
            const int vr0r = (kt * 8 + l) * 72;
            const int vr1r = (kt * 8 + l + 4) * 72;
#pragma unroll
            for (int nt = 0; nt < 8; ++nt) {
                const int vc = nt * 8 + g;
                uint32_t vr0 = __float_as_uint(vs[vr0r + vc]);
                uint32_t vr1 = __float_as_uint(vs[vr1r + vc]);
                uint32_t vi0 = __float_as_uint(vi[vr0r + vc]);
                uint32_t vi1 = __float_as_uint(vi[vr1r + vc]);
                mma8(ore[nt], ap, vr0, vr1);
                mma8(ore[nt], ain, vi0, vi1);
                mma8(oim[nt], ap, vi0, vi1);
                mma8(oim[nt], ai, vr0, vr1);
            }
        }

        asm volatile("cp.async.wait_group 0;" ::: "memory");
        __syncthreads();
    }

    // ---- epilogue: reduce l over the quad, normalize, store ----
    lsum0 += __shfl_xor_sync(0xffffffffu, lsum0, 1);
    lsum0 += __shfl_xor_sync(0xffffffffu, lsum0, 2);
    lsum1 += __shfl_xor_sync(0xffffffffu, lsum1, 1);
    lsum1 += __shfl_xor_sync(0xffffffffu, lsum1, 2);
    const float inv0 = 1.0f / lsum0;
    const float inv1 = 1.0f / lsum1;

    float* OutR = out + hoff;
    float* OutI = out + (size_t)PLANE + hoff;
    const int r0 = (m0 + w * 16 + g) * 64;
    const int r1 = r0 + 8 * 64;
#pragma unroll
    for (int nt = 0; nt < 8; ++nt) {
        int c = nt * 8 + 2 * l;
        *(float2*)(OutR + r0 + c) = make_float2(ore[nt][0] * inv0, ore[nt][1] * inv0);
        *(float2*)(OutI + r0 + c) = make_float2(oim[nt][0] * inv0, oim[nt][1] * inv0);
        *(float2*)(OutR + r1 + c) = make_float2(ore[nt][2] * inv1, ore[nt][3] * inv1);
        *(float2*)(OutI + r1 + c) = make_float2(oim[nt][2] * inv1, oim[nt][3] * inv1);
    }
}

extern "C" void kernel_launch(void* const* d_in, const int* in_sizes, int n_in,
                              void* d_out, int out_size)
{
    (void)in_sizes; (void)n_in; (void)out_size;
    // prepass: tf32-RNA round K/V into scratch (PLANE/4 float4 per array)
    dim3 pgrid(PLANE / 4 / 256, 4);
    round_kv<<<pgrid, 256>>>(
        (const float4*)d_in[2], (const float4*)d_in[3],
        (const float4*)d_in[4], (const float4*)d_in[5]);

    cudaFuncSetAttribute(cvattn_mma, cudaFuncAttributeMaxDynamicSharedMemorySize, SMEM_BYTES);
    dim3 grid(SLEN / 128, 32);
    cvattn_mma<<<grid, 256, SMEM_BYTES>>>(
        (const float*)d_in[0], (const float*)d_in[1], (float*)d_out);
}

// round 9
// speedup vs baseline: 3.3163x; 1.0141x over previous
#include <cuda_runtime.h>
#include <cstdint>

// Complex attention via portable mma.sync tf32 (legacy HMMA on sm_103).
// Round 9: K/V/P smem layouts are fragment-interleaved 16B chunks (prepass-
// baked, bank-swizzled) so every MMA operand gather is ONE conflict-free
// LDS.128 instead of 4 scalar LDS. Math/numerics identical to R8.
#define SLEN 2048
#define PLANE (4*8*2048*64)
#define TEMP_INV 0.125f
#define NT 32
#define SGN 0x80000000u

// smem (uint4 units): K[2 bufs][2048], V[2 bufs][2048], P[8 warps][512]
#define SMEM_BYTES (12288*16)

// prepass output: per (head,tile) 2048 chunks, fragment-interleaved+swizzled
__device__ uint4 gK[32*32*2048];
__device__ uint4 gV[32*32*2048];

static __device__ __forceinline__ void mma8(float* d, const uint32_t* a,
                                            uint32_t b0, uint32_t b1) {
    asm volatile("mma.sync.aligned.m16n8k8.row.col.f32.tf32.tf32.f32 "
                 "{%0,%1,%2,%3},{%4,%5,%6,%7},{%8,%9},{%0,%1,%2,%3};"
                 : "+f"(d[0]), "+f"(d[1]), "+f"(d[2]), "+f"(d[3])
                 : "r"(a[0]), "r"(a[1]), "r"(a[2]), "r"(a[3]), "r"(b0), "r"(b1));
}
static __device__ __forceinline__ uint32_t tf32r(float x) {
    uint32_t u; asm("cvt.rna.tf32.f32 %0, %1;" : "=r"(u) : "f"(x)); return u;
}
static __device__ __forceinline__ void cp16(void* dst, const uint4* src) {
    unsigned a = (unsigned)__cvta_generic_to_shared(dst);
    asm volatile("cp.async.cg.shared.global [%0], [%1], 16;" :: "r"(a), "l"(src));
}

// ---- prepass: K chunks {Kr[d],Kr[d+4],Ki[d],Ki[d+4]} keyed [n][kt][l], swizzled
__global__ __launch_bounds__(256)
void prep_k(const float* __restrict__ kr, const float* __restrict__ ki) {
    int x = blockIdx.x * 256 + threadIdx.x;          // 2,097,152 total
    int l = x & 3, kt = (x >> 2) & 7, n = (x >> 5) & 63;
    int t = (x >> 11) & 31, h = x >> 16;
    int b = (((h << 11) + (t << 6) + n) << 6) + (kt << 3) + l;
    int chunk = (n << 5) + ((kt << 2) ^ ((n & 1) << 2)) + (l ^ ((n >> 1) & 3));
    gK[(((h << 5) + t) << 11) + chunk] =
        make_uint4(tf32r(kr[b]), tf32r(kr[b + 4]), tf32r(ki[b]), tf32r(ki[b + 4]));
}
// ---- prepass: V chunks {Vr[key][d],Vr[key+4][d],Vi..}, keyed [d][kt][l], swizzled
__global__ __launch_bounds__(256)
void prep_v(const float* __restrict__ vr, const float* __restrict__ vi) {
    int x = blockIdx.x * 256 + threadIdx.x;
    int d = x & 63, l = (x >> 6) & 3, kt = (x >> 8) & 7;
    int t = (x >> 11) & 31, h = x >> 16;
    int b = (((h << 11) + (t << 6) + (kt << 3) + l) << 6) + d;
    int chunk = (d << 5) + ((kt << 2) ^ ((d & 1) << 2)) + (l ^ ((d >> 1) & 3));
    gV[(((h << 5) + t) << 11) + chunk] =
        make_uint4(tf32r(vr[b]), tf32r(vr[b + 256]), tf32r(vi[b]), tf32r(vi[b + 256]));
}

__global__ __launch_bounds__(256, 1)
void cvattn_mma(const float* __restrict__ qr_g, const float* __restrict__ qi_g,
                float* __restrict__ out)
{
    extern __shared__ uint4 smem4[];
    const int tid  = threadIdx.x;
    const int w    = tid >> 5;
    const int lane = tid & 31;
    const int g    = lane >> 2;
    const int l    = lane & 3;
    const int bh   = blockIdx.y;
    const size_t hoff = (size_t)bh * (SLEN * 64);
    const int m0 = blockIdx.x << 7;

    const uint4* srcK = gK + ((size_t)bh << 16);   // 32 tiles x 2048 chunks
    const uint4* srcV = gV + ((size_t)bh << 16);

    // per-thread swizzle constants
    const int kx = (g & 1) << 2;                   // XOR on kt*4
    const int bn = (g << 5) + (l ^ ((g >> 1) & 3));// n-row base + swizzled l
    const int rev2l = ((l & 1) << 1) | (l >> 1);   // brev3(2l)
    const int bl = ((l & 1) << 2) | (l & 2);       // brev3(l), l<4

    // ---- Q fragments (persist in registers, tf32 RNA) ----
    uint32_t qa[8][4], qb[8][4];
    {
        const float* Qr = qr_g + hoff;
        const float* Qi = qi_g + hoff;
        const int r0 = (m0 + w * 16 + g) * 64;
        const int r1 = r0 + 8 * 64;
#pragma unroll
        for (int kt = 0; kt < 8; ++kt) {
            int c = kt * 8 + l;
            qa[kt][0] = tf32r(Qr[r0 + c] * TEMP_INV);
            qa[kt][1] = tf32r(Qr[r1 + c] * TEMP_INV);
            qa[kt][2] = tf32r(Qr[r0 + c + 4] * TEMP_INV);
            qa[kt][3] = tf32r(Qr[r1 + c + 4] * TEMP_INV);
            qb[kt][0] = tf32r(Qi[r0 + c] * TEMP_INV);
            qb[kt][1] = tf32r(Qi[r1 + c] * TEMP_INV);
            qb[kt][2] = tf32r(Qi[r0 + c + 4] * TEMP_INV);
            qb[kt][3] = tf32r(Qi[r1 + c + 4] * TEMP_INV);
        }
    }

    float ore[8][4], oim[8][4];
#pragma unroll
    for (int nt = 0; nt < 8; ++nt)
#pragma unroll
        for (int j = 0; j < 4; ++j) { ore[nt][j] = 0.f; oim[nt][j] = 0.f; }
    float lsum0 = 0.f, lsum1 = 0.f;

    // tile 0 load
#pragma unroll
    for (int j = 0; j < 8; ++j) {
        cp16(smem4 + tid + (j << 8),        srcK + tid + (j << 8));
        cp16(smem4 + 4096 + tid + (j << 8), srcV + tid + (j << 8));
    }
    asm volatile("cp.async.commit_group;" ::: "memory");
    asm volatile("cp.async.wait_group 0;" ::: "memory");
    __syncthreads();

    uint4* pw4 = smem4 + 8192 + (w << 9);   // warp-private P: 512 chunks

    for (int t = 0; t < NT; ++t) {
        if (t + 1 < NT) {
            const int nb = (t + 1) & 1, tb = (t + 1) << 11;
#pragma unroll
            for (int j = 0; j < 8; ++j) {
                cp16(smem4 + (nb << 11) + tid + (j << 8),        srcK + tb + tid + (j << 8));
                cp16(smem4 + 4096 + (nb << 11) + tid + (j << 8), srcV + tb + tid + (j << 8));
            }
        }
        asm volatile("cp.async.commit_group;" ::: "memory");

        const uint4* kb = smem4 + ((t & 1) << 11);

        // ---- S = (Q/T) K^T : one LDS.128 per (kt,nt) fragment ----
        float sre[8][4], sim_[8][4];
#pragma unroll
        for (int nt = 0; nt < 8; ++nt)
#pragma unroll
            for (int j = 0; j < 4; ++j) { sre[nt][j] = 0.f; sim_[nt][j] = 0.f; }

#pragma unroll
        for (int kt = 0; kt < 8; ++kt) {
            const int ko = ((kt << 2) ^ kx) + bn;
#pragma unroll
            for (int nt = 0; nt < 8; ++nt) {
                uint4 f = kb[(nt << 8) + ko];
                mma8(sre[nt],  qa[kt], f.x, f.y);
                mma8(sim_[nt], qa[kt], f.z, f.w);
                mma8(sre[nt],  qb[kt], f.z ^ SGN, f.w ^ SGN);
                mma8(sim_[nt], qb[kt], f.x, f.y);
            }
        }

        // ---- softmax on |S|; P chunks {Pr[g],Pr[g+8],Pi[g],Pi[g+8]} ----
#pragma unroll
        for (int nt = 0; nt < 8; ++nt) {
            float pr[4], pi[4];
#pragma unroll
            for (int j = 0; j < 4; ++j) {
                float x = sre[nt][j], y = sim_[nt][j];
                float r2 = fmaf(x, x, y * y);
                float ri = rsqrtf(fmaxf(r2, 1e-24f));
                float e  = __expf(r2 * ri);
                float wt = e * ri;
                pr[j] = __uint_as_float(tf32r(x * wt));
                pi[j] = __uint_as_float(tf32r(y * wt));
                if (j < 2) lsum0 += e; else lsum1 += e;
            }
            int c = (nt << 3) + (l << 1);
            pw4[(c << 3) + (g ^ rev2l)] =
                make_uint4(__float_as_uint(pr[0]), __float_as_uint(pr[2]),
                           __float_as_uint(pi[0]), __float_as_uint(pi[2]));
            pw4[((c + 1) << 3) + (g ^ rev2l ^ 4)] =
                make_uint4(__float_as_uint(pr[1]), __float_as_uint(pr[3]),
                           __float_as_uint(pi[1]), __float_as_uint(pi[3]));
        }
        __syncwarp();

        // ---- O += P V : LDS.128 A-frags (P) and B-frags (V) ----
        const uint4* vb = smem4 + 4096 + ((t & 1) << 11);
#pragma unroll
        for (int kt = 0; kt < 8; ++kt) {
            const int c = (kt << 3) + l;
            uint4 a0 = pw4[(c << 3) + (g ^ bl)];
            uint4 a1 = pw4[((c + 4) << 3) + (g ^ bl ^ 1)];
            uint32_t ap[4]  = {a0.x, a0.y, a1.x, a1.y};
            uint32_t ai[4]  = {a0.z, a0.w, a1.z, a1.w};
            uint32_t ain[4] = {a0.z ^ SGN, a0.w ^ SGN, a1.z ^ SGN, a1.w ^ SGN};
            const int vo = ((kt << 2) ^ kx) + bn;
#pragma unroll
            for (int nt = 0; nt < 8; ++nt) {
                uint4 v = vb[(nt << 8) + vo];
                mma8(ore[nt], ap,  v.x, v.y);
                mma8(oim[nt], ap,  v.z, v.w);
                mma8(ore[nt], ain, v.z, v.w);
                mma8(oim[nt], ai,  v.x, v.y);
            }
        }

        asm volatile("cp.async.wait_group 0;" ::: "memory");
        __syncthreads();
    }

    // ---- epilogue: reduce l over quad, normalize, store ----
    lsum0 += __shfl_xor_sync(0xffffffffu, lsum0, 1);
    lsum0 += __shfl_xor_sync(0xffffffffu, lsum0, 2);
    lsum1 += __shfl_xor_sync(0xffffffffu, lsum1, 1);
    lsum1 += __shfl_xor_sync(0xffffffffu, lsum1, 2);
    const float inv0 = 1.0f / lsum0;
    const float inv1 = 1.0f / lsum1;

    float* OutR = out + hoff;
    float* OutI = out + (size_t)PLANE + hoff;
    const int r0 = (m0 + w * 16 + g) * 64;
    const int r1 = r0 + 8 * 64;
#pragma unroll
    for (int nt = 0; nt < 8; ++nt) {
        int c = nt * 8 + 2 * l;
        *(float2*)(OutR + r0 + c) = make_float2(ore[nt][0] * inv0, ore[nt][1] * inv0);
        *(float2*)(OutI + r0 + c) = make_float2(oim[nt][0] * inv0, oim[nt][1] * inv0);
        *(float2*)(OutR + r1 + c) = make_float2(ore[nt][2] * inv1, ore[nt][3] * inv1);
        *(float2*)(OutI + r1 + c) = make_float2(oim[nt][2] * inv1, oim[nt][3] * inv1);
    }
}

extern "C" void kernel_launch(void* const* d_in, const int* in_sizes, int n_in,
                              void* d_out, int out_size)
{
    (void)in_sizes; (void)n_in; (void)out_size;
    prep_k<<<8192, 256>>>((const float*)d_in[2], (const float*)d_in[3]);
    prep_v<<<8192, 256>>>((const float*)d_in[4], (const float*)d_in[5]);

    cudaFuncSetAttribute(cvattn_mma, cudaFuncAttributeMaxDynamicSharedMemorySize, SMEM_BYTES);
    dim3 grid(SLEN / 128, 32);
    cvattn_mma<<<grid, 256, SMEM_BYTES>>>(
        (const float*)d_in[0], (const float*)d_in[1], (float*)d_out);
}

// round 10
// speedup vs baseline: 6.0889x; 1.8361x over previous
#include <cuda_runtime.h>
#include <cuda_fp16.h>
#include <cstdint>

// Complex attention via portable mma.sync m16n8k16 fp16 (f32 accum).
// Round 10: fp16 operands (same 10-bit mantissa as tf32), K=16 per MMA
// -> half the MMA instructions, half the smem traffic vs R9.
#define SLEN 2048
#define PLANE (4*8*2048*64)
#define TEMP_INV 0.125f
#define NT 32
#define SGNH 0x80008000u

// smem uint4 units: K[2][1024] @0, V[2][1024] @2048, P[8 warps][256] @4096
#define SMEM_BYTES ((4096 + 8*256)*16)   // 98304

// prepass: B-fragment chunks, per (head,tile): 1024 uint4
__device__ uint4 gK[32*32*1024];
__device__ uint4 gV[32*32*1024];

static __device__ __forceinline__ void mma16(float* d, const uint32_t* a,
                                             uint32_t b0, uint32_t b1) {
    asm volatile("mma.sync.aligned.m16n8k16.row.col.f32.f16.f16.f32 "
                 "{%0,%1,%2,%3},{%4,%5,%6,%7},{%8,%9},{%0,%1,%2,%3};"
                 : "+f"(d[0]), "+f"(d[1]), "+f"(d[2]), "+f"(d[3])
                 : "r"(a[0]), "r"(a[1]), "r"(a[2]), "r"(a[3]), "r"(b0), "r"(b1));
}
static __device__ __forceinline__ uint32_t h2u(float x, float y) {
    __half2 h = __floats2half2_rn(x, y);
    return *(uint32_t*)&h;
}
static __device__ __forceinline__ void cp16(void* dst, const uint4* src) {
    unsigned a = (unsigned)__cvta_generic_to_shared(dst);
    asm volatile("cp.async.cg.shared.global [%0], [%1], 16;" :: "r"(a), "l"(src));
}

// x bits: lane[0:5) ktp[5:7) nt[7:10) t[10:15) h[15:20)
__global__ __launch_bounds__(256)
void prep_k(const float* __restrict__ kr, const float* __restrict__ ki) {
    int x = blockIdx.x * 256 + threadIdx.x;
    int lane = x & 31, ktp = (x >> 5) & 3, nt = (x >> 7) & 7;
    int t = (x >> 10) & 31, h = x >> 15;
    int g = lane >> 2, l = lane & 3;
    int row = ((h << 11) + (t << 6) + (nt << 3) + g) << 6;   // *64
    int k0 = (ktp << 4) + 2 * l, k1 = k0 + 8;
    gK[x] = make_uint4(h2u(kr[row + k0], kr[row + k0 + 1]),
                       h2u(kr[row + k1], kr[row + k1 + 1]),
                       h2u(ki[row + k0], ki[row + k0 + 1]),
                       h2u(ki[row + k1], ki[row + k1 + 1]));
}
__global__ __launch_bounds__(256)
void prep_v(const float* __restrict__ vr, const float* __restrict__ vi) {
    int x = blockIdx.x * 256 + threadIdx.x;
    int lane = x & 31, ktp = (x >> 5) & 3, nt = (x >> 7) & 7;
    int t = (x >> 10) & 31, h = x >> 15;
    int g = lane >> 2, l = lane & 3;
    int d = (nt << 3) + g;
    size_t base = ((size_t)h << 17) + d;                     // h*2048*64 + d
    int key0 = ((t << 6) + (ktp << 4) + 2 * l) << 6;         // *64
    int key8 = key0 + (8 << 6);
    gV[x] = make_uint4(h2u(vr[base + key0], vr[base + key0 + 64]),
                       h2u(vr[base + key8], vr[base + key8 + 64]),
                       h2u(vi[base + key0], vi[base + key0 + 64]),
                       h2u(vi[base + key8], vi[base + key8 + 64]));
}

__global__ __launch_bounds__(256, 1)
void cvattn_mma(const float* __restrict__ qr_g, const float* __restrict__ qi_g,
                float* __restrict__ out)
{
    extern __shared__ uint4 smem4[];
    const int tid  = threadIdx.x;
    const int w    = tid >> 5;
    const int lane = tid & 31;
    const int g    = lane >> 2;
    const int l    = lane & 3;
    const int bh   = blockIdx.y;
    const size_t hoff = (size_t)bh * (SLEN * 64);
    const int m0 = blockIdx.x << 7;

    const uint4* srcK = gK + ((size_t)bh << 15);   // 32 tiles x 1024
    const uint4* srcV = gV + ((size_t)bh << 15);

    // ---- Q fragments in fp16 (rows m0+w*16+g, +8), scaled ----
    uint32_t qa[4][4], qb[4][4];
    {
        const float* Q0r = qr_g + hoff + (size_t)(m0 + w * 16 + g) * 64;
        const float* Q1r = Q0r + 8 * 64;
        const float* Q0i = qi_g + hoff + (size_t)(m0 + w * 16 + g) * 64;
        const float* Q1i = Q0i + 8 * 64;
#pragma unroll
        for (int ktp = 0; ktp < 4; ++ktp) {
            int k0 = ktp * 16 + 2 * l, k1 = k0 + 8;
            qa[ktp][0] = h2u(Q0r[k0] * TEMP_INV, Q0r[k0 + 1] * TEMP_INV);
            qa[ktp][1] = h2u(Q1r[k0] * TEMP_INV, Q1r[k0 + 1] * TEMP_INV);
            qa[ktp][2] = h2u(Q0r[k1] * TEMP_INV, Q0r[k1 + 1] * TEMP_INV);
            qa[ktp][3] = h2u(Q1r[k1] * TEMP_INV, Q1r[k1 + 1] * TEMP_INV);
            qb[ktp][0] = h2u(Q0i[k0] * TEMP_INV, Q0i[k0 + 1] * TEMP_INV);
            qb[ktp][1] = h2u(Q1i[k0] * TEMP_INV, Q1i[k0 + 1] * TEMP_INV);
            qb[ktp][2] = h2u(Q0i[k1] * TEMP_INV, Q0i[k1 + 1] * TEMP_INV);
            qb[ktp][3] = h2u(Q1i[k1] * TEMP_INV, Q1i[k1 + 1] * TEMP_INV);
        }
    }

    float ore[8][4], oim[8][4];
#pragma unroll
    for (int nt = 0; nt < 8; ++nt)
#pragma unroll
        for (int j = 0; j < 4; ++j) { ore[nt][j] = 0.f; oim[nt][j] = 0.f; }
    float lsum0 = 0.f, lsum1 = 0.f;

    // tile 0 load: K 1024 + V 1024 chunks
#pragma unroll
    for (int j = 0; j < 4; ++j) {
        cp16(smem4 + tid + (j << 8),        srcK + tid + (j << 8));
        cp16(smem4 + 2048 + tid + (j << 8), srcV + tid + (j << 8));
    }
    asm volatile("cp.async.commit_group;" ::: "memory");
    asm volatile("cp.async.wait_group 0;" ::: "memory");
    __syncthreads();

    uint2* ppr = (uint2*)(smem4 + 4096 + (w << 8));   // P re: [kp 32][g 8] uint2
    uint2* ppi = ppr + 256;                           // P im

    for (int t = 0; t < NT; ++t) {
        if (t + 1 < NT) {
            const int nb = (t + 1) & 1, tb = (t + 1) << 10;
#pragma unroll
            for (int j = 0; j < 4; ++j) {
                cp16(smem4 + (nb << 10) + tid + (j << 8),        srcK + tb + tid + (j << 8));
                cp16(smem4 + 2048 + (nb << 10) + tid + (j << 8), srcV + tb + tid + (j << 8));
            }
        }
        asm volatile("cp.async.commit_group;" ::: "memory");

        const uint4* kb = smem4 + ((t & 1) << 10);

        // ---- S = (Q/T) K^T (complex) ----
        float sre[8][4], sim_[8][4];
#pragma unroll
        for (int nt = 0; nt < 8; ++nt)
#pragma unroll
            for (int j = 0; j < 4; ++j) { sre[nt][j] = 0.f; sim_[nt][j] = 0.f; }

#pragma unroll
        for (int ktp = 0; ktp < 4; ++ktp) {
#pragma unroll
            for (int nt = 0; nt < 8; ++nt) {
                uint4 f = kb[(((nt << 2) + ktp) << 5) + lane];
                mma16(sre[nt],  qa[ktp], f.x, f.y);
                mma16(sim_[nt], qa[ktp], f.z, f.w);
                mma16(sre[nt],  qb[ktp], f.z ^ SGNH, f.w ^ SGNH);
                mma16(sim_[nt], qb[ktp], f.x, f.y);
            }
        }

        // ---- softmax on |S|; P -> warp smem as fp16 pairs ----
#pragma unroll
        for (int nt = 0; nt < 8; ++nt) {
            float pr[4], pi[4];
#pragma unroll
            for (int j = 0; j < 4; ++j) {
                float x = sre[nt][j], y = sim_[nt][j];
                float r2 = fmaf(x, x, y * y);
                float ri = rsqrtf(fmaxf(r2, 1e-24f));
                float e  = __expf(r2 * ri);
                float wt = e * ri;
                pr[j] = x * wt;
                pi[j] = y * wt;
                if (j < 2) lsum0 += e; else lsum1 += e;
            }
            int idx = (((nt << 2) + l) << 3) + g;     // [kp][g]
            ppr[idx] = make_uint2(h2u(pr[0], pr[1]), h2u(pr[2], pr[3]));
            ppi[idx] = make_uint2(h2u(pi[0], pi[1]), h2u(pi[2], pi[3]));
        }
        __syncwarp();

        // ---- O += P V (complex) ----
        const uint4* vb = smem4 + 2048 + ((t & 1) << 10);
#pragma unroll
        for (int ktp = 0; ktp < 4; ++ktp) {
            int i0 = (((ktp << 3) + l) << 3) + g;      // kp = ktp*8+l
            int i1 = i0 + 32;                          // kp + 4
            uint2 u0 = ppr[i0], u1 = ppr[i1];
            uint2 v0 = ppi[i0], v1 = ppi[i1];
            uint32_t ap[4]  = {u0.x, u0.y, u1.x, u1.y};
            uint32_t ai[4]  = {v0.x, v0.y, v1.x, v1.y};
            uint32_t ain[4] = {v0.x ^ SGNH, v0.y ^ SGNH, v1.x ^ SGNH, v1.y ^ SGNH};
#pragma unroll
            for (int nt = 0; nt < 8; ++nt) {
                uint4 v = vb[(((nt << 2) + ktp) << 5) + lane];
                mma16(ore[nt], ap,  v.x, v.y);
                mma16(oim[nt], ap,  v.z, v.w);
                mma16(ore[nt], ain, v.z, v.w);
                mma16(oim[nt], ai,  v.x, v.y);
            }
        }

        asm volatile("cp.async.wait_group 0;" ::: "memory");
        __syncthreads();
    }

    // ---- epilogue ----
    lsum0 += __shfl_xor_sync(0xffffffffu, lsum0, 1);
    lsum0 += __shfl_xor_sync(0xffffffffu, lsum0, 2);
    lsum1 += __shfl_xor_sync(0xffffffffu, lsum1, 1);
    lsum1 += __shfl_xor_sync(0xffffffffu, lsum1, 2);
    const float inv0 = 1.0f / lsum0;
    const float inv1 = 1.0f / lsum1;

    float* OutR = out + hoff;
    float* OutI = out + (size_t)PLANE + hoff;
    const int r0 = (m0 + w * 16 + g) * 64;
    const int r1 = r0 + 8 * 64;
#pragma unroll
    for (int nt = 0; nt < 8; ++nt) {
        int c = nt * 8 + 2 * l;
        *(float2*)(OutR + r0 + c) = make_float2(ore[nt][0] * inv0, ore[nt][1] * inv0);
        *(float2*)(OutI + r0 + c) = make_float2(oim[nt][0] * inv0, oim[nt][1] * inv0);
        *(float2*)(OutR + r1 + c) = make_float2(ore[nt][2] * inv1, ore[nt][3] * inv1);
        *(float2*)(OutI + r1 + c) = make_float2(oim[nt][2] * inv1, oim[nt][3] * inv1);
    }
}

extern "C" void kernel_launch(void* const* d_in, const int* in_sizes, int n_in,
                              void* d_out, int out_size)
{
    (void)in_sizes; (void)n_in; (void)out_size;
    prep_k<<<4096, 256>>>((const float*)d_in[2], (const float*)d_in[3]);
    prep_v<<<4096, 256>>>((const float*)d_in[4], (const float*)d_in[5]);

    cudaFuncSetAttribute(cvattn_mma, cudaFuncAttributeMaxDynamicSharedMemorySize, SMEM_BYTES);
    dim3 grid(SLEN / 128, 32);
    cvattn_mma<<<grid, 256, SMEM_BYTES>>>(
        (const float*)d_in[0], (const float*)d_in[1], (float*)d_out);
}

// round 11
// speedup vs baseline: 7.3401x; 1.2055x over previous
#include <cuda_runtime.h>
#include <cuda_fp16.h>
#include <cstdint>

// Complex attention via portable mma.sync m16n8k16 fp16 (f32 accum).
// Round 11: CTA split to 128 threads / 64 query rows -> 2 CTAs per SM.
// Desynchronized CTAs keep the tensor pipe fed during softmax/barrier phases.
#define SLEN 2048
#define PLANE (4*8*2048*64)
#define TEMP_INV 0.125f
#define NT 32
#define SGNH 0x80008000u

// smem uint4 units: K[2][1024] @0, V[2][1024] @2048, P[4 warps][256] @4096
#define SMEM_BYTES ((4096 + 4*256)*16)   // 81920

// prepass: B-fragment chunks, per (head,tile): 1024 uint4
__device__ uint4 gK[32*32*1024];
__device__ uint4 gV[32*32*1024];

static __device__ __forceinline__ void mma16(float* d, const uint32_t* a,
                                             uint32_t b0, uint32_t b1) {
    asm volatile("mma.sync.aligned.m16n8k16.row.col.f32.f16.f16.f32 "
                 "{%0,%1,%2,%3},{%4,%5,%6,%7},{%8,%9},{%0,%1,%2,%3};"
                 : "+f"(d[0]), "+f"(d[1]), "+f"(d[2]), "+f"(d[3])
                 : "r"(a[0]), "r"(a[1]), "r"(a[2]), "r"(a[3]), "r"(b0), "r"(b1));
}
static __device__ __forceinline__ uint32_t h2u(float x, float y) {
    __half2 h = __floats2half2_rn(x, y);
    return *(uint32_t*)&h;
}
static __device__ __forceinline__ void cp16(void* dst, const uint4* src) {
    unsigned a = (unsigned)__cvta_generic_to_shared(dst);
    asm volatile("cp.async.cg.shared.global [%0], [%1], 16;" :: "r"(a), "l"(src));
}

// x bits: lane[0:5) ktp[5:7) nt[7:10) t[10:15) h[15:20)
__global__ __launch_bounds__(256)
void prep_k(const float* __restrict__ kr, const float* __restrict__ ki) {
    int x = blockIdx.x * 256 + threadIdx.x;
    int lane = x & 31, ktp = (x >> 5) & 3, nt = (x >> 7) & 7;
    int t = (x >> 10) & 31, h = x >> 15;
    int g = lane >> 2, l = lane & 3;
    int row = ((h << 11) + (t << 6) + (nt << 3) + g) << 6;   // *64
    int k0 = (ktp << 4) + 2 * l, k1 = k0 + 8;
    gK[x] = make_uint4(h2u(kr[row + k0], kr[row + k0 + 1]),
                       h2u(kr[row + k1], kr[row + k1 + 1]),
                       h2u(ki[row + k0], ki[row + k0 + 1]),
                       h2u(ki[row + k1], ki[row + k1 + 1]));
}
__global__ __launch_bounds__(256)
void prep_v(const float* __restrict__ vr, const float* __restrict__ vi) {
    int x = blockIdx.x * 256 + threadIdx.x;
    int lane = x & 31, ktp = (x >> 5) & 3, nt = (x >> 7) & 7;
    int t = (x >> 10) & 31, h = x >> 15;
    int g = lane >> 2, l = lane & 3;
    int d = (nt << 3) + g;
    size_t base = ((size_t)h << 17) + d;                     // h*2048*64 + d
    int key0 = ((t << 6) + (ktp << 4) + 2 * l) << 6;         // *64
    int key8 = key0 + (8 << 6);
    gV[x] = make_uint4(h2u(vr[base + key0], vr[base + key0 + 64]),
                       h2u(vr[base + key8], vr[base + key8 + 64]),
                       h2u(vi[base + key0], vi[base + key0 + 64]),
                       h2u(vi[base + key8], vi[base + key8 + 64]));
}

__global__ __launch_bounds__(128, 2)
void cvattn_mma(const float* __restrict__ qr_g, const float* __restrict__ qi_g,
                float* __restrict__ out)
{
    extern __shared__ uint4 smem4[];
    const int tid  = threadIdx.x;
    const int w    = tid >> 5;                 // 0..3
    const int lane = tid & 31;
    const int g    = lane >> 2;
    const int l    = lane & 3;
    const int bh   = blockIdx.y;
    const size_t hoff = (size_t)bh * (SLEN * 64);
    const int m0 = blockIdx.x << 6;            // 64-row query tile

    const uint4* srcK = gK + ((size_t)bh << 15);   // 32 tiles x 1024
    const uint4* srcV = gV + ((size_t)bh << 15);

    // ---- Q fragments in fp16 (rows m0+w*16+g, +8), scaled ----
    uint32_t qa[4][4], qb[4][4];
    {
        const float* Q0r = qr_g + hoff + (size_t)(m0 + w * 16 + g) * 64;
        const float* Q1r = Q0r + 8 * 64;
        const float* Q0i = qi_g + hoff + (size_t)(m0 + w * 16 + g) * 64;
        const float* Q1i = Q0i + 8 * 64;
#pragma unroll
        for (int ktp = 0; ktp < 4; ++ktp) {
            int k0 = ktp * 16 + 2 * l, k1 = k0 + 8;
            qa[ktp][0] = h2u(Q0r[k0] * TEMP_INV, Q0r[k0 + 1] * TEMP_INV);
            qa[ktp][1] = h2u(Q1r[k0] * TEMP_INV, Q1r[k0 + 1] * TEMP_INV);
            qa[ktp][2] = h2u(Q0r[k1] * TEMP_INV, Q0r[k1 + 1] * TEMP_INV);
            qa[ktp][3] = h2u(Q1r[k1] * TEMP_INV, Q1r[k1 + 1] * TEMP_INV);
            qb[ktp][0] = h2u(Q0i[k0] * TEMP_INV, Q0i[k0 + 1] * TEMP_INV);
            qb[ktp][1] = h2u(Q1i[k0] * TEMP_INV, Q1i[k0 + 1] * TEMP_INV);
            qb[ktp][2] = h2u(Q0i[k1] * TEMP_INV, Q0i[k1 + 1] * TEMP_INV);
            qb[ktp][3] = h2u(Q1i[k1] * TEMP_INV, Q1i[k1 + 1] * TEMP_INV);
        }
    }

    float ore[8][4], oim[8][4];
#pragma unroll
    for (int nt = 0; nt < 8; ++nt)
#pragma unroll
        for (int j = 0; j < 4; ++j) { ore[nt][j] = 0.f; oim[nt][j] = 0.f; }
    float lsum0 = 0.f, lsum1 = 0.f;

    // tile 0 load: K 1024 + V 1024 chunks with 128 threads
#pragma unroll
    for (int j = 0; j < 8; ++j) {
        cp16(smem4 + tid + (j << 7),        srcK + tid + (j << 7));
        cp16(smem4 + 2048 + tid + (j << 7), srcV + tid + (j << 7));
    }
    asm volatile("cp.async.commit_group;" ::: "memory");
    asm volatile("cp.async.wait_group 0;" ::: "memory");
    __syncthreads();

    uint2* ppr = (uint2*)(smem4 + 4096 + (w << 8));   // P re: [kp 32][g 8] uint2
    uint2* ppi = ppr + 256;                           // P im

    for (int t = 0; t < NT; ++t) {
        if (t + 1 < NT) {
            const int nb = (t + 1) & 1, tb = (t + 1) << 10;
#pragma unroll
            for (int j = 0; j < 8; ++j) {
                cp16(smem4 + (nb << 10) + tid + (j << 7),        srcK + tb + tid + (j << 7));
                cp16(smem4 + 2048 + (nb << 10) + tid + (j << 7), srcV + tb + tid + (j << 7));
            }
        }
        asm volatile("cp.async.commit_group;" ::: "memory");

        const uint4* kb = smem4 + ((t & 1) << 10);

        // ---- S = (Q/T) K^T (complex) ----
        float sre[8][4], sim_[8][4];
#pragma unroll
        for (int nt = 0; nt < 8; ++nt)
#pragma unroll
            for (int j = 0; j < 4; ++j) { sre[nt][j] = 0.f; sim_[nt][j] = 0.f; }

#pragma unroll
        for (int ktp = 0; ktp < 4; ++ktp) {
#pragma unroll
            for (int nt = 0; nt < 8; ++nt) {
                uint4 f = kb[(((nt << 2) + ktp) << 5) + lane];
                mma16(sre[nt],  qa[ktp], f.x, f.y);
                mma16(sim_[nt], qa[ktp], f.z, f.w);
                mma16(sre[nt],  qb[ktp], f.z ^ SGNH, f.w ^ SGNH);
                mma16(sim_[nt], qb[ktp], f.x, f.y);
            }
        }

        // ---- softmax on |S|; P -> warp smem as fp16 pairs ----
#pragma unroll
        for (int nt = 0; nt < 8; ++nt) {
            float pr[4], pi[4];
#pragma unroll
            for (int j = 0; j < 4; ++j) {
                float x = sre[nt][j], y = sim_[nt][j];
                float r2 = fmaf(x, x, y * y);
                float ri = rsqrtf(fmaxf(r2, 1e-24f));
                float e  = __expf(r2 * ri);
                float wt = e * ri;
                pr[j] = x * wt;
                pi[j] = y * wt;
                if (j < 2) lsum0 += e; else lsum1 += e;
            }
            int idx = (((nt << 2) + l) << 3) + g;     // [kp][g]
            ppr[idx] = make_uint2(h2u(pr[0], pr[1]), h2u(pr[2], pr[3]));
            ppi[idx] = make_uint2(h2u(pi[0], pi[1]), h2u(pi[2], pi[3]));
        }
        __syncwarp();

        // ---- O += P V (complex) ----
        const uint4* vb = smem4 + 2048 + ((t & 1) << 10);
#pragma unroll
        for (int ktp = 0; ktp < 4; ++ktp) {
            int i0 = (((ktp << 3) + l) << 3) + g;      // kp = ktp*8+l
            int i1 = i0 + 32;                          // kp + 4
            uint2 u0 = ppr[i0], u1 = ppr[i1];
            uint2 v0 = ppi[i0], v1 = ppi[i1];
            uint32_t ap[4]  = {u0.x, u0.y, u1.x, u1.y};
            uint32_t ai[4]  = {v0.x, v0.y, v1.x, v1.y};
            uint32_t ain[4] = {v0.x ^ SGNH, v0.y ^ SGNH, v1.x ^ SGNH, v1.y ^ SGNH};
#pragma unroll
            for (int nt = 0; nt < 8; ++nt) {
                uint4 v = vb[(((nt << 2) + ktp) << 5) + lane];
                mma16(ore[nt], ap,  v.x, v.y);
                mma16(oim[nt], ap,  v.z, v.w);
                mma16(ore[nt], ain, v.z, v.w);
                mma16(oim[nt], ai,  v.x, v.y);
            }
        }

        asm volatile("cp.async.wait_group 0;" ::: "memory");
        __syncthreads();
    }

    // ---- epilogue ----
    lsum0 += __shfl_xor_sync(0xffffffffu, lsum0, 1);
    lsum0 += __shfl_xor_sync(0xffffffffu, lsum0, 2);
    lsum1 += __shfl_xor_sync(0xffffffffu, lsum1, 1);
    lsum1 += __shfl_xor_sync(0xffffffffu, lsum1, 2);
    const float inv0 = 1.0f / lsum0;
    const float inv1 = 1.0f / lsum1;

    float* OutR = out + hoff;
    float* OutI = out + (size_t)PLANE + hoff;
    const int r0 = (m0 + w * 16 + g) * 64;
    const int r1 = r0 + 8 * 64;
#pragma unroll
    for (int nt = 0; nt < 8; ++nt) {
        int c = nt * 8 + 2 * l;
        *(float2*)(OutR + r0 + c) = make_float2(ore[nt][0] * inv0, ore[nt][1] * inv0);
        *(float2*)(OutI + r0 + c) = make_float2(oim[nt][0] * inv0, oim[nt][1] * inv0);
        *(float2*)(OutR + r1 + c) = make_float2(ore[nt][2] * inv1, ore[nt][3] * inv1);
        *(float2*)(OutI + r1 + c) = make_float2(oim[nt][2] * inv1, oim[nt][3] * inv1);
    }
}

extern "C" void kernel_launch(void* const* d_in, const int* in_sizes, int n_in,
                              void* d_out, int out_size)
{
    (void)in_sizes; (void)n_in; (void)out_size;
    prep_k<<<4096, 256>>>((const float*)d_in[2], (const float*)d_in[3]);
    prep_v<<<4096, 256>>>((const float*)d_in[4], (const float*)d_in[5]);

    cudaFuncSetAttribute(cvattn_mma, cudaFuncAttributeMaxDynamicSharedMemorySize, SMEM_BYTES);
    dim3 grid(SLEN / 64, 32);
    cvattn_mma<<<grid, 128, SMEM_BYTES>>>(
        (const float*)d_in[0], (const float*)d_in[1], (float*)d_out);
}